// round 10
// baseline (speedup 1.0000x reference)
#include <cuda_runtime.h>
#include <cuda_fp16.h>
#include <mma.h>

using namespace nvcuda;

#define BATCH 2
#define SEQ 2048
#define HEADS 16
#define HDIM 64
#define HIDDEN 1024
#define MTOT (BATCH * SEQ)   // 4096

// Scratch for Q/K/V in [B, H, S, D] fp16 layout (8 MB each).
__device__ __half g_Q[BATCH * HEADS * SEQ * HDIM];
__device__ __half g_K[BATCH * HEADS * SEQ * HDIM];
__device__ __half g_V[BATCH * HEADS * SEQ * HDIM];

// ---------------------------------------------------------------------------
// Fused QKV projection: one launch, blockIdx.z in {0,1,2} selects
//   z=0: Q = (former @ Wq + bq) * 0.125
//   z=1: K =  latter @ Wk + bk
//   z=2: V =  latter @ Wv + bv
// Tile: 128(M) x 64(N), BK=64, 256 threads (8 warps, each 32x32 via 2x2 wmma).
// Software pipeline: LDG(k+1) -> regs | MMA(k) | STS regs -> buf^1 | bar.
// ---------------------------------------------------------------------------
struct GemmSmem {
    union {
        struct {
            __half A[2][128][80];   // ld 80 halves = 160B; 40960 B
            __half Bm[2][64][80];   // 20480 B
        } ab;                       // 61440 B total
        float C[128][72];           // 36864 B (reused after final barrier)
    } u;
};

__global__ __launch_bounds__(256) void qkv_gemm_fused(
    const float* __restrict__ former,
    const float* __restrict__ latter,
    const float* __restrict__ Wq, const float* __restrict__ bq,
    const float* __restrict__ Wk, const float* __restrict__ bk,
    const float* __restrict__ Wv, const float* __restrict__ bv,
    __half* __restrict__ Qd, __half* __restrict__ Kd, __half* __restrict__ Vd)
{
    extern __shared__ char smem_raw[];
    GemmSmem& sm = *reinterpret_cast<GemmSmem*>(smem_raw);

    const int z = blockIdx.z;
    const float* X    = (z == 0) ? former : latter;
    const float* W    = (z == 0) ? Wq : (z == 1) ? Wk : Wv;
    const float* bias = (z == 0) ? bq : (z == 1) ? bk : bv;
    __half* out       = (z == 0) ? Qd : (z == 1) ? Kd : Vd;
    const float scale = (z == 0) ? 0.125f : 1.0f;   // 1/sqrt(64) folded into Q

    const int n0 = blockIdx.x * 64;
    const int m0 = blockIdx.y * 128;
    const int tid = threadIdx.x;
    const int w = tid >> 5;
    const int m_off = (w & 3) * 32;
    const int n_off = (w >> 2) * 32;

    auto ldg_tiles = [&](int kb, float4* ra, float4* rb) {
        const int k0 = kb * 64;
#pragma unroll
        for (int j = 0; j < 8; j++) {
            int i = tid + 256 * j;
            int r = i >> 4;
            int c = (i & 15) * 4;
            ra[j] = *reinterpret_cast<const float4*>(
                X + (size_t)(m0 + r) * HIDDEN + k0 + c);
        }
#pragma unroll
        for (int j = 0; j < 4; j++) {
            int i = tid + 256 * j;
            int r = i >> 4;
            int c = (i & 15) * 4;
            rb[j] = *reinterpret_cast<const float4*>(
                W + (size_t)(k0 + r) * HIDDEN + n0 + c);
        }
    };

    auto sts_tiles = [&](int buf, const float4* ra, const float4* rb) {
#pragma unroll
        for (int j = 0; j < 8; j++) {
            int i = tid + 256 * j;
            int r = i >> 4;
            int c = (i & 15) * 4;
            __half2* dst = reinterpret_cast<__half2*>(&sm.u.ab.A[buf][r][c]);
            dst[0] = __floats2half2_rn(ra[j].x, ra[j].y);
            dst[1] = __floats2half2_rn(ra[j].z, ra[j].w);
        }
#pragma unroll
        for (int j = 0; j < 4; j++) {
            int i = tid + 256 * j;
            int r = i >> 4;
            int c = (i & 15) * 4;
            __half2* dst = reinterpret_cast<__half2*>(&sm.u.ab.Bm[buf][r][c]);
            dst[0] = __floats2half2_rn(rb[j].x, rb[j].y);
            dst[1] = __floats2half2_rn(rb[j].z, rb[j].w);
        }
    };

    wmma::fragment<wmma::accumulator, 16, 16, 16, float> acc[2][2];
#pragma unroll
    for (int i = 0; i < 2; i++)
#pragma unroll
        for (int j = 0; j < 2; j++)
            wmma::fill_fragment(acc[i][j], 0.0f);

    {   // prologue: tile 0 straight to smem
        float4 ra[8], rb[4];
        ldg_tiles(0, ra, rb);
        sts_tiles(0, ra, rb);
    }
    __syncthreads();

    const int NKB = HIDDEN / 64;   // 16
    for (int kb = 0; kb < NKB; kb++) {
        const int buf = kb & 1;

        float4 ra[8], rb[4];
        if (kb + 1 < NKB) ldg_tiles(kb + 1, ra, rb);

#pragma unroll
        for (int kk = 0; kk < 64; kk += 16) {
            wmma::fragment<wmma::matrix_a, 16, 16, 16, __half, wmma::row_major> a0, a1;
            wmma::load_matrix_sync(a0, &sm.u.ab.A[buf][m_off][kk], 80);
            wmma::load_matrix_sync(a1, &sm.u.ab.A[buf][m_off + 16][kk], 80);
            wmma::fragment<wmma::matrix_b, 16, 16, 16, __half, wmma::row_major> b0, b1;
            wmma::load_matrix_sync(b0, &sm.u.ab.Bm[buf][kk][n_off], 80);
            wmma::load_matrix_sync(b1, &sm.u.ab.Bm[buf][kk][n_off + 16], 80);
            wmma::mma_sync(acc[0][0], a0, b0, acc[0][0]);
            wmma::mma_sync(acc[0][1], a0, b1, acc[0][1]);
            wmma::mma_sync(acc[1][0], a1, b0, acc[1][0]);
            wmma::mma_sync(acc[1][1], a1, b1, acc[1][1]);
        }

        if (kb + 1 < NKB) sts_tiles(buf ^ 1, ra, rb);
        __syncthreads();
    }

#pragma unroll
    for (int i = 0; i < 2; i++)
#pragma unroll
        for (int j = 0; j < 2; j++)
            wmma::store_matrix_sync(&sm.u.C[m_off + i * 16][n_off + j * 16],
                                    acc[i][j], 72, wmma::mem_row_major);
    __syncthreads();

    // Bias + scale + fp16 convert + scatter into [B,H,S,D]
#pragma unroll 4
    for (int i = tid; i < 128 * 64; i += 256) {
        int r = i >> 6;
        int c = i & 63;
        int row = m0 + r;
        int col = n0 + c;
        int b = row / SEQ;
        int s = row - b * SEQ;
        int h = col >> 6;
        int d = col & 63;
        float v = (sm.u.C[r][c] + bias[col]) * scale;
        out[(((size_t)(b * HEADS + h)) * SEQ + s) * HDIM + d] = __float2half(v);
    }
}

// ---------------------------------------------------------------------------
// Flash attention: one block = (b, h, 128 q-rows); KV tiles of 64.
// 8 warps (256 threads), each warp owns 16 q-rows. Mask tile staged in smem.
// Pipeline per KV tile:
//   LDG(kt+1)->regs | QK^T | softmax (reg-cached scores; O-rescale SKIPPED
//   when the running max is unchanged) | PV (kk-outer, P loaded once) |
//   STS->buf^1 | bar.
// Softmax/O state stays warp-private; one __syncthreads per tile.
// Scale 1/8 is pre-folded into Q.
// ---------------------------------------------------------------------------
#define QTILE 128

struct AttnSmem {
    __half Ksh[2][64][80];    // 20480 B
    __half Vsh[2][64][80];    // 20480 B
    float  Msh[2][64];        //   512 B  mask tile
    float  Ssh[QTILE][72];    // 36864 B
    __half Psh[QTILE][80];    // 20480 B
    float  Osh[QTILE][72];    // 36864 B
    float  lrow[QTILE];       //   512 B
};                            // ~136 KB -> 1 block/SM, 8 warps

__global__ __launch_bounds__(256) void attn_kernel(
    const __half* __restrict__ Q,
    const __half* __restrict__ K,
    const __half* __restrict__ V,
    const float* __restrict__ mask,
    float* __restrict__ out)
{
    extern __shared__ char smem_raw[];
    AttnSmem* sm = reinterpret_cast<AttnSmem*>(smem_raw);

    const int b  = blockIdx.z;
    const int h  = blockIdx.y;
    const int q0 = blockIdx.x * QTILE;
    const int tid  = threadIdx.x;
    const int lane = tid & 31;
    const int q_off = (tid >> 5) * 16;   // this warp's 16 q-rows

    const size_t headbase = ((size_t)(b * HEADS + h)) * SEQ * HDIM;
    const __half* Qp = Q + headbase + (size_t)q0 * HDIM;
    const __half* Kp = K + headbase;
    const __half* Vp = V + headbase;
    const float*  mp = mask + (size_t)b * SEQ;

    // Warp-private init of this warp's 16 O rows
    float* Oown = &sm->Osh[q_off][0];
#pragma unroll 4
    for (int i = lane; i < 16 * 72; i += 32) Oown[i] = 0.0f;

    // Q fragments live for the whole KV loop (global loads, once)
    wmma::fragment<wmma::matrix_a, 16, 16, 16, __half, wmma::row_major> aq[4];
#pragma unroll
    for (int kk = 0; kk < 4; kk++)
        wmma::load_matrix_sync(aq[kk], Qp + (size_t)q_off * HDIM + kk * 16, HDIM);

    // softmax ownership: lane pair (2i, 2i+1) owns row q_off+i; halves split cols
    const int r     = q_off + (lane >> 1);
    const int halfq = lane & 1;
    const int c0    = halfq * 32;

    float m_r = -1e30f;
    float l_r = 0.0f;

    // Per-thread K/V slots: 2 float4 each (512 float4 per tensor / 256 thr).
    // Mask tile: threads 0..15 carry one float4 each (64 floats).
    auto ldg_kv = [&](int kt, float4* rk, float4* rv, float4& rm) {
        const __half* Ks = Kp + (size_t)kt * 64 * HDIM;
        const __half* Vs = Vp + (size_t)kt * 64 * HDIM;
#pragma unroll
        for (int j = 0; j < 2; j++) {
            int i = tid + 256 * j;
            int rr = i >> 3;
            int cc = (i & 7) * 8;
            rk[j] = *reinterpret_cast<const float4*>(Ks + (size_t)rr * HDIM + cc);
            rv[j] = *reinterpret_cast<const float4*>(Vs + (size_t)rr * HDIM + cc);
        }
        if (tid < 16)
            rm = *reinterpret_cast<const float4*>(mp + kt * 64 + tid * 4);
    };
    auto sts_kv = [&](int buf, const float4* rk, const float4* rv, const float4& rm) {
#pragma unroll
        for (int j = 0; j < 2; j++) {
            int i = tid + 256 * j;
            int rr = i >> 3;
            int cc = (i & 7) * 8;
            *reinterpret_cast<float4*>(&sm->Ksh[buf][rr][cc]) = rk[j];
            *reinterpret_cast<float4*>(&sm->Vsh[buf][rr][cc]) = rv[j];
        }
        if (tid < 16)
            *reinterpret_cast<float4*>(&sm->Msh[buf][tid * 4]) = rm;
    };

    {   // prologue: tile 0 straight to smem
        float4 rk[2], rv[2], rm;
        ldg_kv(0, rk, rv, rm);
        sts_kv(0, rk, rv, rm);
    }
    __syncthreads();

    const int NT = SEQ / 64;
    for (int kt = 0; kt < NT; kt++) {
        const int buf = kt & 1;

        // 1) Issue next tile's LDGs (retire during the MMAs/softmax below)
        float4 rk[2], rv[2], rm;
        if (kt + 1 < NT) ldg_kv(kt + 1, rk, rv, rm);

        // 2) S = Q @ K^T (this warp: 16 q-rows x 64 kv-cols), K from smem
#pragma unroll
        for (int n = 0; n < 4; n++) {
            wmma::fragment<wmma::accumulator, 16, 16, 16, float> acc;
            wmma::fill_fragment(acc, 0.0f);
#pragma unroll
            for (int kk = 0; kk < 4; kk++) {
                wmma::fragment<wmma::matrix_b, 16, 16, 16, __half, wmma::col_major> bf;
                wmma::load_matrix_sync(bf, &sm->Ksh[buf][n * 16][kk * 16], 80);
                wmma::mma_sync(acc, aq[kk], bf, acc);
            }
            wmma::store_matrix_sync(&sm->Ssh[q_off][n * 16], acc, 72, wmma::mem_row_major);
        }
        __syncwarp();

        // 3) online softmax on own rows — scores register-cached, vector smem ops
        float sv[32];
        {
            const float4* srow = reinterpret_cast<const float4*>(&sm->Ssh[r][c0]);
            const float4* mrow4 = reinterpret_cast<const float4*>(&sm->Msh[buf][c0]);
#pragma unroll
            for (int j = 0; j < 8; j++) {
                float4 s4 = srow[j];
                float4 m4 = mrow4[j];
                sv[4*j + 0] = s4.x + m4.x;
                sv[4*j + 1] = s4.y + m4.y;
                sv[4*j + 2] = s4.z + m4.z;
                sv[4*j + 3] = s4.w + m4.w;
            }
        }
        float lm = -1e30f;
#pragma unroll
        for (int c = 0; c < 32; c++) lm = fmaxf(lm, sv[c]);
        lm = fmaxf(lm, __shfl_xor_sync(0xffffffffu, lm, 1));
        // lm is identical on both paired lanes after the shfl reduction.
        const bool max_grew = (lm > m_r);
        float newm = max_grew ? lm : m_r;
        float lsum = 0.0f;
        {
            __half2* prow = reinterpret_cast<__half2*>(&sm->Psh[r][c0]);
#pragma unroll
            for (int j = 0; j < 16; j++) {
                float p0 = __expf(sv[2*j + 0] - newm);
                float p1 = __expf(sv[2*j + 1] - newm);
                prow[j] = __floats2half2_rn(p0, p1);
                lsum += p0 + p1;
            }
        }
        lsum += __shfl_xor_sync(0xffffffffu, lsum, 1);
        if (max_grew) {
            // alpha != 1 only when the running max moved (rare after warm-up)
            float alpha = __expf(m_r - newm);
            float4* orow = reinterpret_cast<float4*>(&sm->Osh[r][c0]);
#pragma unroll
            for (int j = 0; j < 8; j++) {
                float4 o4 = orow[j];
                o4.x *= alpha; o4.y *= alpha; o4.z *= alpha; o4.w *= alpha;
                orow[j] = o4;
            }
            l_r = l_r * alpha + lsum;
            m_r = newm;
        } else {
            l_r += lsum;
        }
        __syncwarp();

        // 4) O += P @ V on own rows, V from smem.
        // kk-outer: all 4 O accumulators live in regs; P fragments loaded ONCE.
        {
            wmma::fragment<wmma::accumulator, 16, 16, 16, float> oc[4];
#pragma unroll
            for (int n = 0; n < 4; n++)
                wmma::load_matrix_sync(oc[n], &sm->Osh[q_off][n * 16], 72,
                                       wmma::mem_row_major);
#pragma unroll
            for (int kk = 0; kk < 4; kk++) {
                wmma::fragment<wmma::matrix_a, 16, 16, 16, __half, wmma::row_major> pa;
                wmma::load_matrix_sync(pa, &sm->Psh[q_off][kk * 16], 80);
#pragma unroll
                for (int n = 0; n < 4; n++) {
                    wmma::fragment<wmma::matrix_b, 16, 16, 16, __half, wmma::row_major> vb;
                    wmma::load_matrix_sync(vb, &sm->Vsh[buf][kk * 16][n * 16], 80);
                    wmma::mma_sync(oc[n], pa, vb, oc[n]);
                }
            }
#pragma unroll
            for (int n = 0; n < 4; n++)
                wmma::store_matrix_sync(&sm->Osh[q_off][n * 16], oc[n], 72,
                                        wmma::mem_row_major);
        }

        // 5) Drain prefetched K/V/mask; one barrier per tile
        if (kt + 1 < NT) sts_kv(buf ^ 1, rk, rv, rm);
        __syncthreads();
    }

    // ---- epilogue (warp-private, vectorized): out[b, q, h*64+d] = O / l ----
    if (halfq == 0) sm->lrow[r] = l_r;
    __syncwarp();
    // 16 rows x 16 float4 per row = 256 float4 per warp; 8 per lane.
#pragma unroll
    for (int i = lane; i < 16 * 16; i += 32) {
        int rr = q_off + (i >> 4);
        int d4 = (i & 15);              // float4 index within the row
        float inv = 1.0f / sm->lrow[rr];
        float4 o4 = *reinterpret_cast<const float4*>(&sm->Osh[rr][d4 * 4]);
        o4.x *= inv; o4.y *= inv; o4.z *= inv; o4.w *= inv;
        *reinterpret_cast<float4*>(
            &out[(((size_t)(b * SEQ + q0 + rr)) * HEADS + h) * HDIM + d4 * 4]) = o4;
    }
}

// ---------------------------------------------------------------------------
// Launch
// ---------------------------------------------------------------------------
extern "C" void kernel_launch(void* const* d_in, const int* in_sizes, int n_in,
                              void* d_out, int out_size)
{
    (void)in_sizes; (void)n_in; (void)out_size;
    const float* former = (const float*)d_in[0];
    const float* latter = (const float*)d_in[1];
    const float* mask   = (const float*)d_in[2];
    const float* Wq     = (const float*)d_in[3];
    const float* bq     = (const float*)d_in[4];
    const float* Wk     = (const float*)d_in[5];
    const float* bk     = (const float*)d_in[6];
    const float* Wv     = (const float*)d_in[7];
    const float* bv     = (const float*)d_in[8];
    float* out = (float*)d_out;

    __half *Qd, *Kd, *Vd;
    cudaGetSymbolAddress((void**)&Qd, g_Q);
    cudaGetSymbolAddress((void**)&Kd, g_K);
    cudaGetSymbolAddress((void**)&Vd, g_V);

    cudaFuncSetAttribute(qkv_gemm_fused,
                         cudaFuncAttributeMaxDynamicSharedMemorySize,
                         (int)sizeof(GemmSmem));
    cudaFuncSetAttribute(attn_kernel,
                         cudaFuncAttributeMaxDynamicSharedMemorySize,
                         (int)sizeof(AttnSmem));

    // One fused launch for Q, K, V projections: grid (16, 32, 3)
    dim3 gemm_grid(HIDDEN / 64, MTOT / 128, 3);
    qkv_gemm_fused<<<gemm_grid, 256, sizeof(GemmSmem)>>>(former, latter,
                                                         Wq, bq, Wk, bk, Wv, bv,
                                                         Qd, Kd, Vd);

    dim3 attn_grid(SEQ / QTILE, HEADS, BATCH);   // (16, 16, 2)
    attn_kernel<<<attn_grid, 256, sizeof(AttnSmem)>>>(Qd, Kd, Vd, mask, out);
}

// round 12
// speedup vs baseline: 1.6575x; 1.6575x over previous
#include <cuda_runtime.h>
#include <cuda_fp16.h>
#include <mma.h>
#include <cstdint>

using namespace nvcuda;

#define BATCH 2
#define SEQ 2048
#define HEADS 16
#define HDIM 64
#define HIDDEN 1024
#define MTOT (BATCH * SEQ)   // 4096

// Scratch for Q/K/V in [B, H, S, D] fp16 layout (8 MB each).
__device__ __half g_Q[BATCH * HEADS * SEQ * HDIM];
__device__ __half g_K[BATCH * HEADS * SEQ * HDIM];
__device__ __half g_V[BATCH * HEADS * SEQ * HDIM];

// ---------------------------------------------------------------------------
// Fused QKV projection: one launch, blockIdx.z picks Q/K/V.
// 128x64 tile, BK=64, reg-staged double-buffered pipeline.
// ---------------------------------------------------------------------------
struct GemmSmem {
    union {
        struct {
            __half A[2][128][80];
            __half Bm[2][64][80];
        } ab;
        float C[128][72];
    } u;
};

__global__ __launch_bounds__(256) void qkv_gemm_fused(
    const float* __restrict__ former,
    const float* __restrict__ latter,
    const float* __restrict__ Wq, const float* __restrict__ bq,
    const float* __restrict__ Wk, const float* __restrict__ bk,
    const float* __restrict__ Wv, const float* __restrict__ bv,
    __half* __restrict__ Qd, __half* __restrict__ Kd, __half* __restrict__ Vd)
{
    extern __shared__ char smem_raw[];
    GemmSmem& sm = *reinterpret_cast<GemmSmem*>(smem_raw);

    const int z = blockIdx.z;
    const float* X    = (z == 0) ? former : latter;
    const float* W    = (z == 0) ? Wq : (z == 1) ? Wk : Wv;
    const float* bias = (z == 0) ? bq : (z == 1) ? bk : bv;
    __half* out       = (z == 0) ? Qd : (z == 1) ? Kd : Vd;
    const float scale = (z == 0) ? 0.125f : 1.0f;

    const int n0 = blockIdx.x * 64;
    const int m0 = blockIdx.y * 128;
    const int tid = threadIdx.x;
    const int w = tid >> 5;
    const int m_off = (w & 3) * 32;
    const int n_off = (w >> 2) * 32;

    auto ldg_tiles = [&](int kb, float4* ra, float4* rb) {
        const int k0 = kb * 64;
#pragma unroll
        for (int j = 0; j < 8; j++) {
            int i = tid + 256 * j;
            int r = i >> 4;
            int c = (i & 15) * 4;
            ra[j] = *reinterpret_cast<const float4*>(
                X + (size_t)(m0 + r) * HIDDEN + k0 + c);
        }
#pragma unroll
        for (int j = 0; j < 4; j++) {
            int i = tid + 256 * j;
            int r = i >> 4;
            int c = (i & 15) * 4;
            rb[j] = *reinterpret_cast<const float4*>(
                W + (size_t)(k0 + r) * HIDDEN + n0 + c);
        }
    };

    auto sts_tiles = [&](int buf, const float4* ra, const float4* rb) {
#pragma unroll
        for (int j = 0; j < 8; j++) {
            int i = tid + 256 * j;
            int r = i >> 4;
            int c = (i & 15) * 4;
            __half2* dst = reinterpret_cast<__half2*>(&sm.u.ab.A[buf][r][c]);
            dst[0] = __floats2half2_rn(ra[j].x, ra[j].y);
            dst[1] = __floats2half2_rn(ra[j].z, ra[j].w);
        }
#pragma unroll
        for (int j = 0; j < 4; j++) {
            int i = tid + 256 * j;
            int r = i >> 4;
            int c = (i & 15) * 4;
            __half2* dst = reinterpret_cast<__half2*>(&sm.u.ab.Bm[buf][r][c]);
            dst[0] = __floats2half2_rn(rb[j].x, rb[j].y);
            dst[1] = __floats2half2_rn(rb[j].z, rb[j].w);
        }
    };

    wmma::fragment<wmma::accumulator, 16, 16, 16, float> acc[2][2];
#pragma unroll
    for (int i = 0; i < 2; i++)
#pragma unroll
        for (int j = 0; j < 2; j++)
            wmma::fill_fragment(acc[i][j], 0.0f);

    {
        float4 ra[8], rb[4];
        ldg_tiles(0, ra, rb);
        sts_tiles(0, ra, rb);
    }
    __syncthreads();

    const int NKB = HIDDEN / 64;
    for (int kb = 0; kb < NKB; kb++) {
        const int buf = kb & 1;

        float4 ra[8], rb[4];
        if (kb + 1 < NKB) ldg_tiles(kb + 1, ra, rb);

#pragma unroll
        for (int kk = 0; kk < 64; kk += 16) {
            wmma::fragment<wmma::matrix_a, 16, 16, 16, __half, wmma::row_major> a0, a1;
            wmma::load_matrix_sync(a0, &sm.u.ab.A[buf][m_off][kk], 80);
            wmma::load_matrix_sync(a1, &sm.u.ab.A[buf][m_off + 16][kk], 80);
            wmma::fragment<wmma::matrix_b, 16, 16, 16, __half, wmma::row_major> b0, b1;
            wmma::load_matrix_sync(b0, &sm.u.ab.Bm[buf][kk][n_off], 80);
            wmma::load_matrix_sync(b1, &sm.u.ab.Bm[buf][kk][n_off + 16], 80);
            wmma::mma_sync(acc[0][0], a0, b0, acc[0][0]);
            wmma::mma_sync(acc[0][1], a0, b1, acc[0][1]);
            wmma::mma_sync(acc[1][0], a1, b0, acc[1][0]);
            wmma::mma_sync(acc[1][1], a1, b1, acc[1][1]);
        }

        if (kb + 1 < NKB) sts_tiles(buf ^ 1, ra, rb);
        __syncthreads();
    }

#pragma unroll
    for (int i = 0; i < 2; i++)
#pragma unroll
        for (int j = 0; j < 2; j++)
            wmma::store_matrix_sync(&sm.u.C[m_off + i * 16][n_off + j * 16],
                                    acc[i][j], 72, wmma::mem_row_major);
    __syncthreads();

#pragma unroll 4
    for (int i = tid; i < 128 * 64; i += 256) {
        int r = i >> 6;
        int c = i & 63;
        int row = m0 + r;
        int col = n0 + c;
        int b = row / SEQ;
        int s = row - b * SEQ;
        int h = col >> 6;
        int d = col & 63;
        float v = (sm.u.C[r][c] + bias[col]) * scale;
        out[(((size_t)(b * HEADS + h)) * SEQ + s) * HDIM + d] = __float2half(v);
    }
}

// ---------------------------------------------------------------------------
// Flash attention v2: raw mma.sync.m16n8k16, register-resident S/P/O.
// Block = (b, h, 128 q-rows); 8 warps, each warp owns 16 q-rows.
// Smem holds ONLY double-buffered K/V tiles (+mask); S, softmax, P, O live
// entirely in registers using the documented mma fragment layouts.
// Pipeline: LDG(kt+1)->regs | S=QK^T | softmax(regs) | O+=PV | STS | bar.
// ---------------------------------------------------------------------------
#define QTILE 128
#define KVT 64
#define KPITCH 72   // halfs; 144B row pitch -> conflict-free ldmatrix

struct AttnSmem {
    __half Ksh[2][KVT][KPITCH];   // 18432 B
    __half Vsh[2][KVT][KPITCH];   // 18432 B
    float  Msh[2][KVT];           //   512 B
};                                // ~37.4 KB -> 2 blocks/SM (reg-capped)

__device__ __forceinline__ uint32_t smem_u32(const void* p) {
    return (uint32_t)__cvta_generic_to_shared(p);
}
__device__ __forceinline__ void ldsm4(uint32_t& r0, uint32_t& r1,
                                      uint32_t& r2, uint32_t& r3, uint32_t a) {
    asm volatile("ldmatrix.sync.aligned.m8n8.x4.shared.b16 {%0,%1,%2,%3}, [%4];"
                 : "=r"(r0), "=r"(r1), "=r"(r2), "=r"(r3) : "r"(a));
}
__device__ __forceinline__ void ldsm4t(uint32_t& r0, uint32_t& r1,
                                       uint32_t& r2, uint32_t& r3, uint32_t a) {
    asm volatile("ldmatrix.sync.aligned.m8n8.x4.trans.shared.b16 {%0,%1,%2,%3}, [%4];"
                 : "=r"(r0), "=r"(r1), "=r"(r2), "=r"(r3) : "r"(a));
}
__device__ __forceinline__ void mma16816(float* c, const uint32_t* a,
                                         uint32_t b0, uint32_t b1) {
    asm volatile(
        "mma.sync.aligned.m16n8k16.row.col.f32.f16.f16.f32 "
        "{%0,%1,%2,%3}, {%4,%5,%6,%7}, {%8,%9}, {%0,%1,%2,%3};"
        : "+f"(c[0]), "+f"(c[1]), "+f"(c[2]), "+f"(c[3])
        : "r"(a[0]), "r"(a[1]), "r"(a[2]), "r"(a[3]), "r"(b0), "r"(b1));
}
__device__ __forceinline__ uint32_t packh2(float x, float y) {
    __half2 h = __floats2half2_rn(x, y);
    return *reinterpret_cast<uint32_t*>(&h);
}

__global__ __launch_bounds__(256, 2) void attn_kernel(
    const __half* __restrict__ Q,
    const __half* __restrict__ K,
    const __half* __restrict__ V,
    const float* __restrict__ mask,
    float* __restrict__ out)
{
    extern __shared__ char smem_raw[];
    AttnSmem* sm = reinterpret_cast<AttnSmem*>(smem_raw);

    const int b  = blockIdx.z;
    const int h  = blockIdx.y;
    const int q0 = blockIdx.x * QTILE;
    const int tid  = threadIdx.x;
    const int lane = tid & 31;
    const int q_off = (tid >> 5) * 16;   // this warp's 16 q-rows

    const size_t headbase = ((size_t)(b * HEADS + h)) * SEQ * HDIM;
    const __half* Qp = Q + headbase + (size_t)q0 * HDIM;
    const __half* Kp = K + headbase;
    const __half* Vp = V + headbase;
    const float*  mp = mask + (size_t)b * SEQ;

    const int qr = lane >> 2;        // fragment row within 8 (rows qr, qr+8)
    const int qc = (lane & 3) * 2;   // fragment col pair base

    // ---- Q -> A fragments, loaded once directly from global ----
    // a0:(r,k0-7) a1:(r+8,k0-7) a2:(r,k8-15) a3:(r+8,k8-15)
    uint32_t aq[4][4];
#pragma unroll
    for (int kk = 0; kk < 4; kk++) {
        const __half* base = Qp + (size_t)(q_off + qr) * HDIM + kk * 16 + qc;
        aq[kk][0] = *reinterpret_cast<const uint32_t*>(base);
        aq[kk][1] = *reinterpret_cast<const uint32_t*>(base + 8 * HDIM);
        aq[kk][2] = *reinterpret_cast<const uint32_t*>(base + 8);
        aq[kk][3] = *reinterpret_cast<const uint32_t*>(base + 8 * HDIM + 8);
    }

    // Register-resident O accumulator: 8 d-tiles x 4 floats
    float Ot[8][4];
#pragma unroll
    for (int n = 0; n < 8; n++)
#pragma unroll
        for (int j = 0; j < 4; j++) Ot[n][j] = 0.0f;

    float m0 = -1e30f, m1 = -1e30f;   // running max, rows qr and qr+8
    float l0 = 0.0f,   l1 = 0.0f;     // running sum

    // ldmatrix lane-address components
    const int g   = lane >> 3;       // which 8x8 matrix this lane addresses
    const int rig = lane & 7;        // row within that matrix

    // K/V/mask cooperative staging (pitch KPITCH)
    auto ldg_kv = [&](int kt, float4* rk, float4* rv, float4& rm) {
        const __half* Ks = Kp + (size_t)kt * KVT * HDIM;
        const __half* Vs = Vp + (size_t)kt * KVT * HDIM;
#pragma unroll
        for (int j = 0; j < 2; j++) {
            int i = tid + 256 * j;
            int rr = i >> 3;
            int cc = (i & 7) * 8;
            rk[j] = *reinterpret_cast<const float4*>(Ks + (size_t)rr * HDIM + cc);
            rv[j] = *reinterpret_cast<const float4*>(Vs + (size_t)rr * HDIM + cc);
        }
        if (tid < 16)
            rm = *reinterpret_cast<const float4*>(mp + kt * KVT + tid * 4);
    };
    auto sts_kv = [&](int buf, const float4* rk, const float4* rv, const float4& rm) {
#pragma unroll
        for (int j = 0; j < 2; j++) {
            int i = tid + 256 * j;
            int rr = i >> 3;
            int cc = (i & 7) * 8;
            *reinterpret_cast<float4*>(&sm->Ksh[buf][rr][cc]) = rk[j];
            *reinterpret_cast<float4*>(&sm->Vsh[buf][rr][cc]) = rv[j];
        }
        if (tid < 16)
            *reinterpret_cast<float4*>(&sm->Msh[buf][tid * 4]) = rm;
    };

    {
        float4 rk[2], rv[2], rm = make_float4(0.f, 0.f, 0.f, 0.f);
        ldg_kv(0, rk, rv, rm);
        sts_kv(0, rk, rv, rm);
    }
    __syncthreads();

    const int NT = SEQ / KVT;
    for (int kt = 0; kt < NT; kt++) {
        const int buf = kt & 1;

        float4 rk[2], rv[2], rm = make_float4(0.f, 0.f, 0.f, 0.f);
        if (kt + 1 < NT) ldg_kv(kt + 1, rk, rv, rm);

        const uint32_t kbase = smem_u32(&sm->Ksh[buf][0][0]);
        const uint32_t vbase = smem_u32(&sm->Vsh[buf][0][0]);

        // ---- S = Q @ K^T : 8 n8-tiles x 4 floats, in registers ----
        float St[8][4];
#pragma unroll
        for (int n = 0; n < 8; n++)
#pragma unroll
            for (int j = 0; j < 4; j++) St[n][j] = 0.0f;

#pragma unroll
        for (int kk = 0; kk < 4; kk++) {
#pragma unroll
            for (int np = 0; np < 4; np++) {
                // lanes 0-7: tile(2np, d lo); 8-15: (2np, d hi);
                // 16-23: (2np+1, d lo); 24-31: (2np+1, d hi)
                int row = 8 * (2 * np + (g >> 1)) + rig;
                int col = 16 * kk + (g & 1) * 8;
                uint32_t addr = kbase + (uint32_t)(row * KPITCH + col) * 2u;
                uint32_t b0, b1, b2, b3;
                ldsm4(b0, b1, b2, b3, addr);
                mma16816(St[2 * np],     aq[kk], b0, b1);
                mma16816(St[2 * np + 1], aq[kk], b2, b3);
            }
        }

        // ---- softmax in registers ----
        float mx0 = -1e30f, mx1 = -1e30f;
#pragma unroll
        for (int n = 0; n < 8; n++) {
            float mv0 = sm->Msh[buf][8 * n + qc];
            float mv1 = sm->Msh[buf][8 * n + qc + 1];
            St[n][0] += mv0; St[n][1] += mv1;
            St[n][2] += mv0; St[n][3] += mv1;
            mx0 = fmaxf(mx0, fmaxf(St[n][0], St[n][1]));
            mx1 = fmaxf(mx1, fmaxf(St[n][2], St[n][3]));
        }
        // quad reduction (lanes sharing the same fragment row)
        mx0 = fmaxf(mx0, __shfl_xor_sync(0xffffffffu, mx0, 1));
        mx0 = fmaxf(mx0, __shfl_xor_sync(0xffffffffu, mx0, 2));
        mx1 = fmaxf(mx1, __shfl_xor_sync(0xffffffffu, mx1, 1));
        mx1 = fmaxf(mx1, __shfl_xor_sync(0xffffffffu, mx1, 2));

        float newm0 = fmaxf(m0, mx0);
        float newm1 = fmaxf(m1, mx1);

        // exp -> P (packed half2 for the PV A-operand), partial sums
        uint32_t Pt[8][2];
        float s0 = 0.0f, s1 = 0.0f;
#pragma unroll
        for (int n = 0; n < 8; n++) {
            float p0 = __expf(St[n][0] - newm0);
            float p1 = __expf(St[n][1] - newm0);
            float p2 = __expf(St[n][2] - newm1);
            float p3 = __expf(St[n][3] - newm1);
            Pt[n][0] = packh2(p0, p1);
            Pt[n][1] = packh2(p2, p3);
            s0 += p0 + p1;
            s1 += p2 + p3;
        }
        s0 += __shfl_xor_sync(0xffffffffu, s0, 1);
        s0 += __shfl_xor_sync(0xffffffffu, s0, 2);
        s1 += __shfl_xor_sync(0xffffffffu, s1, 1);
        s1 += __shfl_xor_sync(0xffffffffu, s1, 2);

        // rescale O in registers (alpha==1 when max unchanged)
        float alpha0 = __expf(m0 - newm0);
        float alpha1 = __expf(m1 - newm1);
#pragma unroll
        for (int n = 0; n < 8; n++) {
            Ot[n][0] *= alpha0; Ot[n][1] *= alpha0;
            Ot[n][2] *= alpha1; Ot[n][3] *= alpha1;
        }
        l0 = l0 * alpha0 + s0;
        l1 = l1 * alpha1 + s1;
        m0 = newm0;
        m1 = newm1;

        // ---- O += P @ V ----
#pragma unroll
        for (int kk = 0; kk < 4; kk++) {
            // A operand for kv chunk kk: S-tiles 2kk (k 0-7) and 2kk+1 (k 8-15)
            uint32_t ap[4] = { Pt[2 * kk][0], Pt[2 * kk][1],
                               Pt[2 * kk + 1][0], Pt[2 * kk + 1][1] };
#pragma unroll
            for (int dp = 0; dp < 4; dp++) {
                // trans tiles: lanes 0-7: (kv lo, d 2dp); 8-15: (kv hi, d 2dp);
                // 16-23: (kv lo, d 2dp+1); 24-31: (kv hi, d 2dp+1)
                int row = 16 * kk + (g & 1) * 8 + rig;
                int col = 8 * (2 * dp + (g >> 1));
                uint32_t addr = vbase + (uint32_t)(row * KPITCH + col) * 2u;
                uint32_t b0, b1, b2, b3;
                ldsm4t(b0, b1, b2, b3, addr);
                mma16816(Ot[2 * dp],     ap, b0, b1);
                mma16816(Ot[2 * dp + 1], ap, b2, b3);
            }
        }

        if (kt + 1 < NT) sts_kv(buf ^ 1, rk, rv, rm);
        __syncthreads();
    }

    // ---- epilogue: registers straight to global ----
    const float inv0 = 1.0f / l0;
    const float inv1 = 1.0f / l1;
    const size_t row0 = ((size_t)(b * SEQ + q0 + q_off + qr) * HEADS + h) * (size_t)HDIM;
    const size_t row1 = row0 + (size_t)8 * HEADS * HDIM;   // row qr+8
#pragma unroll
    for (int n = 0; n < 8; n++) {
        int d = 8 * n + qc;
        *reinterpret_cast<float2*>(&out[row0 + d]) =
            make_float2(Ot[n][0] * inv0, Ot[n][1] * inv0);
        *reinterpret_cast<float2*>(&out[row1 + d]) =
            make_float2(Ot[n][2] * inv1, Ot[n][3] * inv1);
    }
}

// ---------------------------------------------------------------------------
// Launch
// ---------------------------------------------------------------------------
extern "C" void kernel_launch(void* const* d_in, const int* in_sizes, int n_in,
                              void* d_out, int out_size)
{
    (void)in_sizes; (void)n_in; (void)out_size;
    const float* former = (const float*)d_in[0];
    const float* latter = (const float*)d_in[1];
    const float* mask   = (const float*)d_in[2];
    const float* Wq     = (const float*)d_in[3];
    const float* bq     = (const float*)d_in[4];
    const float* Wk     = (const float*)d_in[5];
    const float* bk     = (const float*)d_in[6];
    const float* Wv     = (const float*)d_in[7];
    const float* bv     = (const float*)d_in[8];
    float* out = (float*)d_out;

    __half *Qd, *Kd, *Vd;
    cudaGetSymbolAddress((void**)&Qd, g_Q);
    cudaGetSymbolAddress((void**)&Kd, g_K);
    cudaGetSymbolAddress((void**)&Vd, g_V);

    cudaFuncSetAttribute(qkv_gemm_fused,
                         cudaFuncAttributeMaxDynamicSharedMemorySize,
                         (int)sizeof(GemmSmem));
    cudaFuncSetAttribute(attn_kernel,
                         cudaFuncAttributeMaxDynamicSharedMemorySize,
                         (int)sizeof(AttnSmem));

    dim3 gemm_grid(HIDDEN / 64, MTOT / 128, 3);
    qkv_gemm_fused<<<gemm_grid, 256, sizeof(GemmSmem)>>>(former, latter,
                                                         Wq, bq, Wk, bk, Wv, bv,
                                                         Qd, Kd, Vd);

    dim3 attn_grid(SEQ / QTILE, HEADS, BATCH);   // (16, 16, 2)
    attn_kernel<<<attn_grid, 256, sizeof(AttnSmem)>>>(Qd, Kd, Vd, mask, out);
}

// round 16
// speedup vs baseline: 2.0717x; 1.2499x over previous
#include <cuda_runtime.h>
#include <cuda_fp16.h>
#include <mma.h>
#include <cstdint>

using namespace nvcuda;

#define BATCH 2
#define SEQ 2048
#define HEADS 16
#define HDIM 64
#define HIDDEN 1024
#define MTOT (BATCH * SEQ)   // 4096

// Scratch: Q/K/V fp16 [B,H,S,D] (8 MB each); fp16 copies of inputs/weights.
__device__ __half g_Q[BATCH * HEADS * SEQ * HDIM];
__device__ __half g_K[BATCH * HEADS * SEQ * HDIM];
__device__ __half g_V[BATCH * HEADS * SEQ * HDIM];
__device__ __half g_X16[2 * MTOT * HIDDEN];        // [0]=former16, [1]=latter16
__device__ __half g_W16[3 * HIDDEN * HIDDEN];      // Wq16, Wk16, Wv16

// ---------------------------------------------------------------------------
// One-shot fp32 -> fp16 conversion (hoisted out of the GEMM mainloop).
// blockIdx.y selects tensor; grid-stride over float4.
// ---------------------------------------------------------------------------
__global__ __launch_bounds__(256) void convert_fp16(
    const float* __restrict__ former, const float* __restrict__ latter,
    const float* __restrict__ Wq, const float* __restrict__ Wk,
    const float* __restrict__ Wv)
{
    const int z = blockIdx.y;
    const float* src;
    __half* dst;
    int n;   // element count
    if (z == 0)      { src = former; dst = g_X16;                    n = MTOT * HIDDEN; }
    else if (z == 1) { src = latter; dst = g_X16 + MTOT * HIDDEN;    n = MTOT * HIDDEN; }
    else if (z == 2) { src = Wq;     dst = g_W16;                    n = HIDDEN * HIDDEN; }
    else if (z == 3) { src = Wk;     dst = g_W16 + HIDDEN * HIDDEN;  n = HIDDEN * HIDDEN; }
    else             { src = Wv;     dst = g_W16 + 2 * HIDDEN * HIDDEN; n = HIDDEN * HIDDEN; }

    const int n4 = n >> 2;
    for (int i = blockIdx.x * blockDim.x + threadIdx.x; i < n4;
         i += gridDim.x * blockDim.x) {
        float4 v = reinterpret_cast<const float4*>(src)[i];
        reinterpret_cast<__half2*>(dst)[2 * i]     = __floats2half2_rn(v.x, v.y);
        reinterpret_cast<__half2*>(dst)[2 * i + 1] = __floats2half2_rn(v.z, v.w);
    }
}

// ---------------------------------------------------------------------------
// cp.async helpers
// ---------------------------------------------------------------------------
__device__ __forceinline__ uint32_t smem_u32(const void* p) {
    return (uint32_t)__cvta_generic_to_shared(p);
}
__device__ __forceinline__ void cp_async16(uint32_t s, const void* g) {
    asm volatile("cp.async.cg.shared.global [%0], [%1], 16;" :: "r"(s), "l"(g));
}
__device__ __forceinline__ void cp_commit() {
    asm volatile("cp.async.commit_group;");
}
__device__ __forceinline__ void cp_wait_all() {
    asm volatile("cp.async.wait_group 0;");
}

// ---------------------------------------------------------------------------
// Fused QKV projection v2: fp16 inputs, cp.async 2-stage pipeline.
// Block tile 128(M) x 128(N), BK=64; 8 warps, each 64x32 (4x2 wmma frags).
// One __syncthreads per k-block. blockIdx.z selects Q/K/V.
// ---------------------------------------------------------------------------
#define APITCH 72    // halfs, 144B: conflict-free ldmatrix, 16B multiple
#define BPITCH 136   // halfs, 272B: conflict-free ldmatrix, 16B multiple

struct GemmSmem {
    union {
        struct {
            __half A[2][128][APITCH];   // 36864 B
            __half B[2][64][BPITCH];    // 34816 B
        } ab;                           // 71680 B
        float C[128][132];              // 67584 B (epilogue staging)
    } u;
};

__global__ __launch_bounds__(256, 2) void qkv_gemm_fused(
    const float* __restrict__ bq, const float* __restrict__ bk,
    const float* __restrict__ bv,
    __half* __restrict__ Qd, __half* __restrict__ Kd, __half* __restrict__ Vd)
{
    extern __shared__ char smem_raw[];
    GemmSmem& sm = *reinterpret_cast<GemmSmem*>(smem_raw);

    const int z = blockIdx.z;
    const __half* X = g_X16 + (size_t)(z == 0 ? 0 : 1) * MTOT * HIDDEN;
    const __half* W = g_W16 + (size_t)z * HIDDEN * HIDDEN;
    const float* bias = (z == 0) ? bq : (z == 1) ? bk : bv;
    __half* out      = (z == 0) ? Qd : (z == 1) ? Kd : Vd;
    const float scale = (z == 0) ? 0.125f : 1.0f;   // 1/sqrt(64) folded into Q

    const int n0 = blockIdx.x * 128;
    const int m0 = blockIdx.y * 128;
    const int tid = threadIdx.x;
    const int w = tid >> 5;
    const int m_off = (w >> 2) * 64;   // warp rows: 0 or 64
    const int n_off = (w & 3) * 32;    // warp cols: 0,32,64,96

    // cp.async issue for k-block kb into stage s.
    // A tile: 128 rows x 64 halfs = 1024 16B-chunks; B: 64 x 128 = 1024 chunks.
    auto issue = [&](int kb, int s) {
        const int k0 = kb * 64;
#pragma unroll
        for (int j = 0; j < 4; j++) {
            int c = tid + 256 * j;
            int row = c >> 3;
            int col = (c & 7) * 8;
            cp_async16(smem_u32(&sm.u.ab.A[s][row][col]),
                       X + (size_t)(m0 + row) * HIDDEN + k0 + col);
        }
#pragma unroll
        for (int j = 0; j < 4; j++) {
            int c = tid + 256 * j;
            int row = c >> 4;
            int col = (c & 15) * 8;
            cp_async16(smem_u32(&sm.u.ab.B[s][row][col]),
                       W + (size_t)(k0 + row) * HIDDEN + n0 + col);
        }
        cp_commit();
    };

    wmma::fragment<wmma::accumulator, 16, 16, 16, float> acc[4][2];
#pragma unroll
    for (int i = 0; i < 4; i++)
#pragma unroll
        for (int j = 0; j < 2; j++)
            wmma::fill_fragment(acc[i][j], 0.0f);

    issue(0, 0);

    const int NKB = HIDDEN / 64;   // 16
    for (int kb = 0; kb < NKB; kb++) {
        const int buf = kb & 1;

        cp_wait_all();        // stage kb data arrived
        __syncthreads();      // visible to all; prev compute done

        if (kb + 1 < NKB) issue(kb + 1, buf ^ 1);   // overlaps compute below

#pragma unroll
        for (int kk = 0; kk < 64; kk += 16) {
            wmma::fragment<wmma::matrix_b, 16, 16, 16, __half, wmma::row_major> b0, b1;
            wmma::load_matrix_sync(b0, &sm.u.ab.B[buf][kk][n_off], BPITCH);
            wmma::load_matrix_sync(b1, &sm.u.ab.B[buf][kk][n_off + 16], BPITCH);
#pragma unroll
            for (int mi = 0; mi < 4; mi++) {
                wmma::fragment<wmma::matrix_a, 16, 16, 16, __half, wmma::row_major> a;
                wmma::load_matrix_sync(a, &sm.u.ab.A[buf][m_off + mi * 16][kk], APITCH);
                wmma::mma_sync(acc[mi][0], a, b0, acc[mi][0]);
                wmma::mma_sync(acc[mi][1], a, b1, acc[mi][1]);
            }
        }
    }
    __syncthreads();   // all MMAs done before union reuse

    // Stage accumulators to shared
#pragma unroll
    for (int mi = 0; mi < 4; mi++)
#pragma unroll
        for (int ni = 0; ni < 2; ni++)
            wmma::store_matrix_sync(&sm.u.C[m_off + mi * 16][n_off + ni * 16],
                                    acc[mi][ni], 132, wmma::mem_row_major);
    __syncthreads();

    // Bias + scale + fp16 convert + scatter into [B,H,S,D]
#pragma unroll 4
    for (int i = tid; i < 128 * 128; i += 256) {
        int r = i >> 7;
        int c = i & 127;
        int row = m0 + r;
        int col = n0 + c;
        int b = row >> 11;          // /SEQ
        int s = row & (SEQ - 1);
        int h = col >> 6;
        int d = col & 63;
        float v = (sm.u.C[r][c] + bias[col]) * scale;
        out[(((size_t)(b * HEADS + h)) * SEQ + s) * HDIM + d] = __float2half(v);
    }
}

// ---------------------------------------------------------------------------
// Flash attention (unchanged from round 12 — 161us, verified).
// Raw mma.sync.m16n8k16, register-resident S/P/O; smem only K/V/mask.
// ---------------------------------------------------------------------------
#define QTILE 128
#define KVT 64
#define KPITCH 72

struct AttnSmem {
    __half Ksh[2][KVT][KPITCH];
    __half Vsh[2][KVT][KPITCH];
    float  Msh[2][KVT];
};

__device__ __forceinline__ void ldsm4(uint32_t& r0, uint32_t& r1,
                                      uint32_t& r2, uint32_t& r3, uint32_t a) {
    asm volatile("ldmatrix.sync.aligned.m8n8.x4.shared.b16 {%0,%1,%2,%3}, [%4];"
                 : "=r"(r0), "=r"(r1), "=r"(r2), "=r"(r3) : "r"(a));
}
__device__ __forceinline__ void ldsm4t(uint32_t& r0, uint32_t& r1,
                                       uint32_t& r2, uint32_t& r3, uint32_t a) {
    asm volatile("ldmatrix.sync.aligned.m8n8.x4.trans.shared.b16 {%0,%1,%2,%3}, [%4];"
                 : "=r"(r0), "=r"(r1), "=r"(r2), "=r"(r3) : "r"(a));
}
__device__ __forceinline__ void mma16816(float* c, const uint32_t* a,
                                         uint32_t b0, uint32_t b1) {
    asm volatile(
        "mma.sync.aligned.m16n8k16.row.col.f32.f16.f16.f32 "
        "{%0,%1,%2,%3}, {%4,%5,%6,%7}, {%8,%9}, {%0,%1,%2,%3};"
        : "+f"(c[0]), "+f"(c[1]), "+f"(c[2]), "+f"(c[3])
        : "r"(a[0]), "r"(a[1]), "r"(a[2]), "r"(a[3]), "r"(b0), "r"(b1));
}
__device__ __forceinline__ uint32_t packh2(float x, float y) {
    __half2 h = __floats2half2_rn(x, y);
    return *reinterpret_cast<uint32_t*>(&h);
}

__global__ __launch_bounds__(256, 2) void attn_kernel(
    const __half* __restrict__ Q,
    const __half* __restrict__ K,
    const __half* __restrict__ V,
    const float* __restrict__ mask,
    float* __restrict__ out)
{
    extern __shared__ char smem_raw[];
    AttnSmem* sm = reinterpret_cast<AttnSmem*>(smem_raw);

    const int b  = blockIdx.z;
    const int h  = blockIdx.y;
    const int q0 = blockIdx.x * QTILE;
    const int tid  = threadIdx.x;
    const int lane = tid & 31;
    const int q_off = (tid >> 5) * 16;

    const size_t headbase = ((size_t)(b * HEADS + h)) * SEQ * HDIM;
    const __half* Qp = Q + headbase + (size_t)q0 * HDIM;
    const __half* Kp = K + headbase;
    const __half* Vp = V + headbase;
    const float*  mp = mask + (size_t)b * SEQ;

    const int qr = lane >> 2;
    const int qc = (lane & 3) * 2;

    uint32_t aq[4][4];
#pragma unroll
    for (int kk = 0; kk < 4; kk++) {
        const __half* base = Qp + (size_t)(q_off + qr) * HDIM + kk * 16 + qc;
        aq[kk][0] = *reinterpret_cast<const uint32_t*>(base);
        aq[kk][1] = *reinterpret_cast<const uint32_t*>(base + 8 * HDIM);
        aq[kk][2] = *reinterpret_cast<const uint32_t*>(base + 8);
        aq[kk][3] = *reinterpret_cast<const uint32_t*>(base + 8 * HDIM + 8);
    }

    float Ot[8][4];
#pragma unroll
    for (int n = 0; n < 8; n++)
#pragma unroll
        for (int j = 0; j < 4; j++) Ot[n][j] = 0.0f;

    float m0 = -1e30f, m1 = -1e30f;
    float l0 = 0.0f,   l1 = 0.0f;

    const int g   = lane >> 3;
    const int rig = lane & 7;

    auto ldg_kv = [&](int kt, float4* rk, float4* rv, float4& rm) {
        const __half* Ks = Kp + (size_t)kt * KVT * HDIM;
        const __half* Vs = Vp + (size_t)kt * KVT * HDIM;
#pragma unroll
        for (int j = 0; j < 2; j++) {
            int i = tid + 256 * j;
            int rr = i >> 3;
            int cc = (i & 7) * 8;
            rk[j] = *reinterpret_cast<const float4*>(Ks + (size_t)rr * HDIM + cc);
            rv[j] = *reinterpret_cast<const float4*>(Vs + (size_t)rr * HDIM + cc);
        }
        if (tid < 16)
            rm = *reinterpret_cast<const float4*>(mp + kt * KVT + tid * 4);
    };
    auto sts_kv = [&](int buf, const float4* rk, const float4* rv, const float4& rm) {
#pragma unroll
        for (int j = 0; j < 2; j++) {
            int i = tid + 256 * j;
            int rr = i >> 3;
            int cc = (i & 7) * 8;
            *reinterpret_cast<float4*>(&sm->Ksh[buf][rr][cc]) = rk[j];
            *reinterpret_cast<float4*>(&sm->Vsh[buf][rr][cc]) = rv[j];
        }
        if (tid < 16)
            *reinterpret_cast<float4*>(&sm->Msh[buf][tid * 4]) = rm;
    };

    {
        float4 rk[2], rv[2], rm = make_float4(0.f, 0.f, 0.f, 0.f);
        ldg_kv(0, rk, rv, rm);
        sts_kv(0, rk, rv, rm);
    }
    __syncthreads();

    const int NT = SEQ / KVT;
    for (int kt = 0; kt < NT; kt++) {
        const int buf = kt & 1;

        float4 rk[2], rv[2], rm = make_float4(0.f, 0.f, 0.f, 0.f);
        if (kt + 1 < NT) ldg_kv(kt + 1, rk, rv, rm);

        const uint32_t kbase = smem_u32(&sm->Ksh[buf][0][0]);
        const uint32_t vbase = smem_u32(&sm->Vsh[buf][0][0]);

        float St[8][4];
#pragma unroll
        for (int n = 0; n < 8; n++)
#pragma unroll
            for (int j = 0; j < 4; j++) St[n][j] = 0.0f;

#pragma unroll
        for (int kk = 0; kk < 4; kk++) {
#pragma unroll
            for (int np = 0; np < 4; np++) {
                int row = 8 * (2 * np + (g >> 1)) + rig;
                int col = 16 * kk + (g & 1) * 8;
                uint32_t addr = kbase + (uint32_t)(row * KPITCH + col) * 2u;
                uint32_t b0, b1, b2, b3;
                ldsm4(b0, b1, b2, b3, addr);
                mma16816(St[2 * np],     aq[kk], b0, b1);
                mma16816(St[2 * np + 1], aq[kk], b2, b3);
            }
        }

        float mx0 = -1e30f, mx1 = -1e30f;
#pragma unroll
        for (int n = 0; n < 8; n++) {
            float mv0 = sm->Msh[buf][8 * n + qc];
            float mv1 = sm->Msh[buf][8 * n + qc + 1];
            St[n][0] += mv0; St[n][1] += mv1;
            St[n][2] += mv0; St[n][3] += mv1;
            mx0 = fmaxf(mx0, fmaxf(St[n][0], St[n][1]));
            mx1 = fmaxf(mx1, fmaxf(St[n][2], St[n][3]));
        }
        mx0 = fmaxf(mx0, __shfl_xor_sync(0xffffffffu, mx0, 1));
        mx0 = fmaxf(mx0, __shfl_xor_sync(0xffffffffu, mx0, 2));
        mx1 = fmaxf(mx1, __shfl_xor_sync(0xffffffffu, mx1, 1));
        mx1 = fmaxf(mx1, __shfl_xor_sync(0xffffffffu, mx1, 2));

        float newm0 = fmaxf(m0, mx0);
        float newm1 = fmaxf(m1, mx1);

        uint32_t Pt[8][2];
        float s0 = 0.0f, s1 = 0.0f;
#pragma unroll
        for (int n = 0; n < 8; n++) {
            float p0 = __expf(St[n][0] - newm0);
            float p1 = __expf(St[n][1] - newm0);
            float p2 = __expf(St[n][2] - newm1);
            float p3 = __expf(St[n][3] - newm1);
            Pt[n][0] = packh2(p0, p1);
            Pt[n][1] = packh2(p2, p3);
            s0 += p0 + p1;
            s1 += p2 + p3;
        }
        s0 += __shfl_xor_sync(0xffffffffu, s0, 1);
        s0 += __shfl_xor_sync(0xffffffffu, s0, 2);
        s1 += __shfl_xor_sync(0xffffffffu, s1, 1);
        s1 += __shfl_xor_sync(0xffffffffu, s1, 2);

        float alpha0 = __expf(m0 - newm0);
        float alpha1 = __expf(m1 - newm1);
#pragma unroll
        for (int n = 0; n < 8; n++) {
            Ot[n][0] *= alpha0; Ot[n][1] *= alpha0;
            Ot[n][2] *= alpha1; Ot[n][3] *= alpha1;
        }
        l0 = l0 * alpha0 + s0;
        l1 = l1 * alpha1 + s1;
        m0 = newm0;
        m1 = newm1;

#pragma unroll
        for (int kk = 0; kk < 4; kk++) {
            uint32_t ap[4] = { Pt[2 * kk][0], Pt[2 * kk][1],
                               Pt[2 * kk + 1][0], Pt[2 * kk + 1][1] };
#pragma unroll
            for (int dp = 0; dp < 4; dp++) {
                int row = 16 * kk + (g & 1) * 8 + rig;
                int col = 8 * (2 * dp + (g >> 1));
                uint32_t addr = vbase + (uint32_t)(row * KPITCH + col) * 2u;
                uint32_t b0, b1, b2, b3;
                ldsm4t(b0, b1, b2, b3, addr);
                mma16816(Ot[2 * dp],     ap, b0, b1);
                mma16816(Ot[2 * dp + 1], ap, b2, b3);
            }
        }

        if (kt + 1 < NT) sts_kv(buf ^ 1, rk, rv, rm);
        __syncthreads();
    }

    const float inv0 = 1.0f / l0;
    const float inv1 = 1.0f / l1;
    const size_t row0 = ((size_t)(b * SEQ + q0 + q_off + qr) * HEADS + h) * (size_t)HDIM;
    const size_t row1 = row0 + (size_t)8 * HEADS * HDIM;
#pragma unroll
    for (int n = 0; n < 8; n++) {
        int d = 8 * n + qc;
        *reinterpret_cast<float2*>(&out[row0 + d]) =
            make_float2(Ot[n][0] * inv0, Ot[n][1] * inv0);
        *reinterpret_cast<float2*>(&out[row1 + d]) =
            make_float2(Ot[n][2] * inv1, Ot[n][3] * inv1);
    }
}

// ---------------------------------------------------------------------------
// Launch
// ---------------------------------------------------------------------------
extern "C" void kernel_launch(void* const* d_in, const int* in_sizes, int n_in,
                              void* d_out, int out_size)
{
    (void)in_sizes; (void)n_in; (void)out_size;
    const float* former = (const float*)d_in[0];
    const float* latter = (const float*)d_in[1];
    const float* mask   = (const float*)d_in[2];
    const float* Wq     = (const float*)d_in[3];
    const float* bq     = (const float*)d_in[4];
    const float* Wk     = (const float*)d_in[5];
    const float* bk     = (const float*)d_in[6];
    const float* Wv     = (const float*)d_in[7];
    const float* bv     = (const float*)d_in[8];
    float* out = (float*)d_out;

    __half *Qd, *Kd, *Vd;
    cudaGetSymbolAddress((void**)&Qd, g_Q);
    cudaGetSymbolAddress((void**)&Kd, g_K);
    cudaGetSymbolAddress((void**)&Vd, g_V);

    cudaFuncSetAttribute(qkv_gemm_fused,
                         cudaFuncAttributeMaxDynamicSharedMemorySize,
                         (int)sizeof(GemmSmem));
    cudaFuncSetAttribute(attn_kernel,
                         cudaFuncAttributeMaxDynamicSharedMemorySize,
                         (int)sizeof(AttnSmem));

    // 1) fp32 -> fp16 conversion (X former/latter + 3 weight matrices)
    dim3 conv_grid(256, 5);
    convert_fp16<<<conv_grid, 256>>>(former, latter, Wq, Wk, Wv);

    // 2) QKV projection: grid (8, 32, 3), 128x128 tiles
    dim3 gemm_grid(HIDDEN / 128, MTOT / 128, 3);
    qkv_gemm_fused<<<gemm_grid, 256, sizeof(GemmSmem)>>>(bq, bk, bv, Qd, Kd, Vd);

    // 3) attention
    dim3 attn_grid(SEQ / QTILE, HEADS, BATCH);   // (16, 16, 2)
    attn_kernel<<<attn_grid, 256, sizeof(AttnSmem)>>>(Qd, Kd, Vd, mask, out);
}

// round 17
// speedup vs baseline: 2.2461x; 1.0842x over previous
#include <cuda_runtime.h>
#include <cuda_fp16.h>
#include <mma.h>
#include <cstdint>

using namespace nvcuda;

#define BATCH 2
#define SEQ 2048
#define HEADS 16
#define HDIM 64
#define HIDDEN 1024
#define MTOT (BATCH * SEQ)   // 4096
#define LOG2E 1.44269504088896340736f

// Scratch: Q/K/V fp16 [B,H,S,D] (8 MB each); fp16 copies of inputs/weights.
__device__ __half g_Q[BATCH * HEADS * SEQ * HDIM];
__device__ __half g_K[BATCH * HEADS * SEQ * HDIM];
__device__ __half g_V[BATCH * HEADS * SEQ * HDIM];
__device__ __half g_X16[2 * MTOT * HIDDEN];        // [0]=former16, [1]=latter16
__device__ __half g_W16[3 * HIDDEN * HIDDEN];      // Wq16, Wk16, Wv16

// ---------------------------------------------------------------------------
// One-shot fp32 -> fp16 conversion (verified round 16: 14.2us).
// ---------------------------------------------------------------------------
__global__ __launch_bounds__(256) void convert_fp16(
    const float* __restrict__ former, const float* __restrict__ latter,
    const float* __restrict__ Wq, const float* __restrict__ Wk,
    const float* __restrict__ Wv)
{
    const int z = blockIdx.y;
    const float* src;
    __half* dst;
    int n;
    if (z == 0)      { src = former; dst = g_X16;                    n = MTOT * HIDDEN; }
    else if (z == 1) { src = latter; dst = g_X16 + MTOT * HIDDEN;    n = MTOT * HIDDEN; }
    else if (z == 2) { src = Wq;     dst = g_W16;                    n = HIDDEN * HIDDEN; }
    else if (z == 3) { src = Wk;     dst = g_W16 + HIDDEN * HIDDEN;  n = HIDDEN * HIDDEN; }
    else             { src = Wv;     dst = g_W16 + 2 * HIDDEN * HIDDEN; n = HIDDEN * HIDDEN; }

    const int n4 = n >> 2;
    for (int i = blockIdx.x * blockDim.x + threadIdx.x; i < n4;
         i += gridDim.x * blockDim.x) {
        float4 v = reinterpret_cast<const float4*>(src)[i];
        reinterpret_cast<__half2*>(dst)[2 * i]     = __floats2half2_rn(v.x, v.y);
        reinterpret_cast<__half2*>(dst)[2 * i + 1] = __floats2half2_rn(v.z, v.w);
    }
}

// ---------------------------------------------------------------------------
// cp.async helpers
// ---------------------------------------------------------------------------
__device__ __forceinline__ uint32_t smem_u32(const void* p) {
    return (uint32_t)__cvta_generic_to_shared(p);
}
__device__ __forceinline__ void cp_async16(uint32_t s, const void* g) {
    asm volatile("cp.async.cg.shared.global [%0], [%1], 16;" :: "r"(s), "l"(g));
}
__device__ __forceinline__ void cp_commit() {
    asm volatile("cp.async.commit_group;");
}
__device__ __forceinline__ void cp_wait_all() {
    asm volatile("cp.async.wait_group 0;");
}
__device__ __forceinline__ void cp_wait1() {
    asm volatile("cp.async.wait_group 1;");
}

// ---------------------------------------------------------------------------
// Fused QKV projection (verified round 16: ~87us). fp16 inputs, cp.async
// 2-stage pipeline, 128x128 tiles. blockIdx.z selects Q/K/V.
// Q scale now folds in LOG2E for the exp2-domain softmax.
// ---------------------------------------------------------------------------
#define APITCH 72    // halfs, 144B: conflict-free ldmatrix, 16B multiple
#define BPITCH 136   // halfs, 272B: conflict-free ldmatrix, 16B multiple

struct GemmSmem {
    union {
        struct {
            __half A[2][128][APITCH];   // 36864 B
            __half B[2][64][BPITCH];    // 34816 B
        } ab;                           // 71680 B
        float C[128][132];              // 67584 B (epilogue staging)
    } u;
};

__global__ __launch_bounds__(256, 2) void qkv_gemm_fused(
    const float* __restrict__ bq, const float* __restrict__ bk,
    const float* __restrict__ bv,
    __half* __restrict__ Qd, __half* __restrict__ Kd, __half* __restrict__ Vd)
{
    extern __shared__ char smem_raw[];
    GemmSmem& sm = *reinterpret_cast<GemmSmem*>(smem_raw);

    const int z = blockIdx.z;
    const __half* X = g_X16 + (size_t)(z == 0 ? 0 : 1) * MTOT * HIDDEN;
    const __half* W = g_W16 + (size_t)z * HIDDEN * HIDDEN;
    const float* bias = (z == 0) ? bq : (z == 1) ? bk : bv;
    __half* out      = (z == 0) ? Qd : (z == 1) ? Kd : Vd;
    // Q: 1/sqrt(64) * log2(e) folded in (softmax runs in exp2 domain)
    const float scale = (z == 0) ? 0.125f * LOG2E : 1.0f;

    const int n0 = blockIdx.x * 128;
    const int m0 = blockIdx.y * 128;
    const int tid = threadIdx.x;
    const int w = tid >> 5;
    const int m_off = (w >> 2) * 64;
    const int n_off = (w & 3) * 32;

    auto issue = [&](int kb, int s) {
        const int k0 = kb * 64;
#pragma unroll
        for (int j = 0; j < 4; j++) {
            int c = tid + 256 * j;
            int row = c >> 3;
            int col = (c & 7) * 8;
            cp_async16(smem_u32(&sm.u.ab.A[s][row][col]),
                       X + (size_t)(m0 + row) * HIDDEN + k0 + col);
        }
#pragma unroll
        for (int j = 0; j < 4; j++) {
            int c = tid + 256 * j;
            int row = c >> 4;
            int col = (c & 15) * 8;
            cp_async16(smem_u32(&sm.u.ab.B[s][row][col]),
                       W + (size_t)(k0 + row) * HIDDEN + n0 + col);
        }
        cp_commit();
    };

    wmma::fragment<wmma::accumulator, 16, 16, 16, float> acc[4][2];
#pragma unroll
    for (int i = 0; i < 4; i++)
#pragma unroll
        for (int j = 0; j < 2; j++)
            wmma::fill_fragment(acc[i][j], 0.0f);

    issue(0, 0);

    const int NKB = HIDDEN / 64;   // 16
    for (int kb = 0; kb < NKB; kb++) {
        const int buf = kb & 1;

        cp_wait_all();
        __syncthreads();

        if (kb + 1 < NKB) issue(kb + 1, buf ^ 1);

#pragma unroll
        for (int kk = 0; kk < 64; kk += 16) {
            wmma::fragment<wmma::matrix_b, 16, 16, 16, __half, wmma::row_major> b0, b1;
            wmma::load_matrix_sync(b0, &sm.u.ab.B[buf][kk][n_off], BPITCH);
            wmma::load_matrix_sync(b1, &sm.u.ab.B[buf][kk][n_off + 16], BPITCH);
#pragma unroll
            for (int mi = 0; mi < 4; mi++) {
                wmma::fragment<wmma::matrix_a, 16, 16, 16, __half, wmma::row_major> a;
                wmma::load_matrix_sync(a, &sm.u.ab.A[buf][m_off + mi * 16][kk], APITCH);
                wmma::mma_sync(acc[mi][0], a, b0, acc[mi][0]);
                wmma::mma_sync(acc[mi][1], a, b1, acc[mi][1]);
            }
        }
    }
    __syncthreads();

#pragma unroll
    for (int mi = 0; mi < 4; mi++)
#pragma unroll
        for (int ni = 0; ni < 2; ni++)
            wmma::store_matrix_sync(&sm.u.C[m_off + mi * 16][n_off + ni * 16],
                                    acc[mi][ni], 132, wmma::mem_row_major);
    __syncthreads();

#pragma unroll 4
    for (int i = tid; i < 128 * 128; i += 256) {
        int r = i >> 7;
        int c = i & 127;
        int row = m0 + r;
        int col = n0 + c;
        int b = row >> 11;
        int s = row & (SEQ - 1);
        int h = col >> 6;
        int d = col & 63;
        float v = (sm.u.C[r][c] + bias[col]) * scale;
        out[(((size_t)(b * HEADS + h)) * SEQ + s) * HDIM + d] = __float2half(v);
    }
}

// ---------------------------------------------------------------------------
// Flash attention v3: cp.async 3-stage K/V/mask pipeline + exp2-domain
// softmax. Raw mma.sync.m16n8k16, register-resident S/P/O.
// Block = (b, h, 128 q-rows); 8 warps, each owns 16 q-rows.
// ---------------------------------------------------------------------------
#define QTILE 128
#define KVT 64
#define KPITCH 72
#define NSTAGE 3

struct AttnSmem {
    __half Ksh[NSTAGE][KVT][KPITCH];   // 27648 B
    __half Vsh[NSTAGE][KVT][KPITCH];   // 27648 B
    float  Msh[NSTAGE][KVT];           //   768 B
};                                     // ~54.8 KB -> 2 blocks/SM

__device__ __forceinline__ void ldsm4(uint32_t& r0, uint32_t& r1,
                                      uint32_t& r2, uint32_t& r3, uint32_t a) {
    asm volatile("ldmatrix.sync.aligned.m8n8.x4.shared.b16 {%0,%1,%2,%3}, [%4];"
                 : "=r"(r0), "=r"(r1), "=r"(r2), "=r"(r3) : "r"(a));
}
__device__ __forceinline__ void ldsm4t(uint32_t& r0, uint32_t& r1,
                                       uint32_t& r2, uint32_t& r3, uint32_t a) {
    asm volatile("ldmatrix.sync.aligned.m8n8.x4.trans.shared.b16 {%0,%1,%2,%3}, [%4];"
                 : "=r"(r0), "=r"(r1), "=r"(r2), "=r"(r3) : "r"(a));
}
__device__ __forceinline__ void mma16816(float* c, const uint32_t* a,
                                         uint32_t b0, uint32_t b1) {
    asm volatile(
        "mma.sync.aligned.m16n8k16.row.col.f32.f16.f16.f32 "
        "{%0,%1,%2,%3}, {%4,%5,%6,%7}, {%8,%9}, {%0,%1,%2,%3};"
        : "+f"(c[0]), "+f"(c[1]), "+f"(c[2]), "+f"(c[3])
        : "r"(a[0]), "r"(a[1]), "r"(a[2]), "r"(a[3]), "r"(b0), "r"(b1));
}
__device__ __forceinline__ uint32_t packh2(float x, float y) {
    __half2 h = __floats2half2_rn(x, y);
    return *reinterpret_cast<uint32_t*>(&h);
}

__global__ __launch_bounds__(256, 2) void attn_kernel(
    const __half* __restrict__ Q,
    const __half* __restrict__ K,
    const __half* __restrict__ V,
    const float* __restrict__ mask,
    float* __restrict__ out)
{
    extern __shared__ char smem_raw[];
    AttnSmem* sm = reinterpret_cast<AttnSmem*>(smem_raw);

    const int b  = blockIdx.z;
    const int h  = blockIdx.y;
    const int q0 = blockIdx.x * QTILE;
    const int tid  = threadIdx.x;
    const int lane = tid & 31;
    const int q_off = (tid >> 5) * 16;

    const size_t headbase = ((size_t)(b * HEADS + h)) * SEQ * HDIM;
    const __half* Qp = Q + headbase + (size_t)q0 * HDIM;
    const __half* Kp = K + headbase;
    const __half* Vp = V + headbase;
    const float*  mp = mask + (size_t)b * SEQ;

    const int qr = lane >> 2;
    const int qc = (lane & 3) * 2;

    // Q -> A fragments, loaded once from global
    uint32_t aq[4][4];
#pragma unroll
    for (int kk = 0; kk < 4; kk++) {
        const __half* base = Qp + (size_t)(q_off + qr) * HDIM + kk * 16 + qc;
        aq[kk][0] = *reinterpret_cast<const uint32_t*>(base);
        aq[kk][1] = *reinterpret_cast<const uint32_t*>(base + 8 * HDIM);
        aq[kk][2] = *reinterpret_cast<const uint32_t*>(base + 8);
        aq[kk][3] = *reinterpret_cast<const uint32_t*>(base + 8 * HDIM + 8);
    }

    float Ot[8][4];
#pragma unroll
    for (int n = 0; n < 8; n++)
#pragma unroll
        for (int j = 0; j < 4; j++) Ot[n][j] = 0.0f;

    float m0 = -1e30f, m1 = -1e30f;   // running max (log2 domain)
    float l0 = 0.0f,   l1 = 0.0f;

    const int g   = lane >> 3;
    const int rig = lane & 7;

    // cp.async staging of one K/V/mask tile into stage s
    auto issue_kv = [&](int kt, int s) {
        const __half* Ks = Kp + (size_t)kt * KVT * HDIM;
        const __half* Vs = Vp + (size_t)kt * KVT * HDIM;
#pragma unroll
        for (int j = 0; j < 2; j++) {
            int i = tid + 256 * j;
            int rr = i >> 3;
            int cc = (i & 7) * 8;
            cp_async16(smem_u32(&sm->Ksh[s][rr][cc]), Ks + (size_t)rr * HDIM + cc);
            cp_async16(smem_u32(&sm->Vsh[s][rr][cc]), Vs + (size_t)rr * HDIM + cc);
        }
        if (tid < 16)
            cp_async16(smem_u32(&sm->Msh[s][tid * 4]), mp + kt * KVT + tid * 4);
        cp_commit();
    };

    issue_kv(0, 0);
    issue_kv(1, 1);

    const int NT = SEQ / KVT;   // 32
    for (int kt = 0; kt < NT; kt++) {
        const int st = kt % NSTAGE;

        // stage kt complete (tail: drain everything)
        if (kt + 1 < NT) cp_wait1(); else cp_wait_all();
        __syncthreads();   // also proves all warps done with stage (kt+2)%3's prior use

        if (kt + 2 < NT) issue_kv(kt + 2, (kt + 2) % NSTAGE);

        const uint32_t kbase = smem_u32(&sm->Ksh[st][0][0]);
        const uint32_t vbase = smem_u32(&sm->Vsh[st][0][0]);

        // ---- S = Q @ K^T (log2-domain: Q pre-scaled by 0.125*log2e) ----
        float St[8][4];
#pragma unroll
        for (int n = 0; n < 8; n++)
#pragma unroll
            for (int j = 0; j < 4; j++) St[n][j] = 0.0f;

#pragma unroll
        for (int kk = 0; kk < 4; kk++) {
#pragma unroll
            for (int np = 0; np < 4; np++) {
                int row = 8 * (2 * np + (g >> 1)) + rig;
                int col = 16 * kk + (g & 1) * 8;
                uint32_t addr = kbase + (uint32_t)(row * KPITCH + col) * 2u;
                uint32_t b0, b1, b2, b3;
                ldsm4(b0, b1, b2, b3, addr);
                mma16816(St[2 * np],     aq[kk], b0, b1);
                mma16816(St[2 * np + 1], aq[kk], b2, b3);
            }
        }

        // ---- softmax in registers (exp2 domain; mask scaled by log2e) ----
        float mx0 = -1e30f, mx1 = -1e30f;
#pragma unroll
        for (int n = 0; n < 8; n++) {
            float mv0 = sm->Msh[st][8 * n + qc] * LOG2E;
            float mv1 = sm->Msh[st][8 * n + qc + 1] * LOG2E;
            St[n][0] += mv0; St[n][1] += mv1;
            St[n][2] += mv0; St[n][3] += mv1;
            mx0 = fmaxf(mx0, fmaxf(St[n][0], St[n][1]));
            mx1 = fmaxf(mx1, fmaxf(St[n][2], St[n][3]));
        }
        mx0 = fmaxf(mx0, __shfl_xor_sync(0xffffffffu, mx0, 1));
        mx0 = fmaxf(mx0, __shfl_xor_sync(0xffffffffu, mx0, 2));
        mx1 = fmaxf(mx1, __shfl_xor_sync(0xffffffffu, mx1, 1));
        mx1 = fmaxf(mx1, __shfl_xor_sync(0xffffffffu, mx1, 2));

        float newm0 = fmaxf(m0, mx0);
        float newm1 = fmaxf(m1, mx1);

        uint32_t Pt[8][2];
        float s0 = 0.0f, s1 = 0.0f;
#pragma unroll
        for (int n = 0; n < 8; n++) {
            float p0 = exp2f(St[n][0] - newm0);
            float p1 = exp2f(St[n][1] - newm0);
            float p2 = exp2f(St[n][2] - newm1);
            float p3 = exp2f(St[n][3] - newm1);
            Pt[n][0] = packh2(p0, p1);
            Pt[n][1] = packh2(p2, p3);
            s0 += p0 + p1;
            s1 += p2 + p3;
        }
        s0 += __shfl_xor_sync(0xffffffffu, s0, 1);
        s0 += __shfl_xor_sync(0xffffffffu, s0, 2);
        s1 += __shfl_xor_sync(0xffffffffu, s1, 1);
        s1 += __shfl_xor_sync(0xffffffffu, s1, 2);

        float alpha0 = exp2f(m0 - newm0);
        float alpha1 = exp2f(m1 - newm1);
#pragma unroll
        for (int n = 0; n < 8; n++) {
            Ot[n][0] *= alpha0; Ot[n][1] *= alpha0;
            Ot[n][2] *= alpha1; Ot[n][3] *= alpha1;
        }
        l0 = l0 * alpha0 + s0;
        l1 = l1 * alpha1 + s1;
        m0 = newm0;
        m1 = newm1;

        // ---- O += P @ V ----
#pragma unroll
        for (int kk = 0; kk < 4; kk++) {
            uint32_t ap[4] = { Pt[2 * kk][0], Pt[2 * kk][1],
                               Pt[2 * kk + 1][0], Pt[2 * kk + 1][1] };
#pragma unroll
            for (int dp = 0; dp < 4; dp++) {
                int row = 16 * kk + (g & 1) * 8 + rig;
                int col = 8 * (2 * dp + (g >> 1));
                uint32_t addr = vbase + (uint32_t)(row * KPITCH + col) * 2u;
                uint32_t b0, b1, b2, b3;
                ldsm4t(b0, b1, b2, b3, addr);
                mma16816(Ot[2 * dp],     ap, b0, b1);
                mma16816(Ot[2 * dp + 1], ap, b2, b3);
            }
        }
    }

    // ---- epilogue: registers straight to global ----
    const float inv0 = 1.0f / l0;
    const float inv1 = 1.0f / l1;
    const size_t row0 = ((size_t)(b * SEQ + q0 + q_off + qr) * HEADS + h) * (size_t)HDIM;
    const size_t row1 = row0 + (size_t)8 * HEADS * HDIM;
#pragma unroll
    for (int n = 0; n < 8; n++) {
        int d = 8 * n + qc;
        *reinterpret_cast<float2*>(&out[row0 + d]) =
            make_float2(Ot[n][0] * inv0, Ot[n][1] * inv0);
        *reinterpret_cast<float2*>(&out[row1 + d]) =
            make_float2(Ot[n][2] * inv1, Ot[n][3] * inv1);
    }
}

// ---------------------------------------------------------------------------
// Launch
// ---------------------------------------------------------------------------
extern "C" void kernel_launch(void* const* d_in, const int* in_sizes, int n_in,
                              void* d_out, int out_size)
{
    (void)in_sizes; (void)n_in; (void)out_size;
    const float* former = (const float*)d_in[0];
    const float* latter = (const float*)d_in[1];
    const float* mask   = (const float*)d_in[2];
    const float* Wq     = (const float*)d_in[3];
    const float* bq     = (const float*)d_in[4];
    const float* Wk     = (const float*)d_in[5];
    const float* bk     = (const float*)d_in[6];
    const float* Wv     = (const float*)d_in[7];
    const float* bv     = (const float*)d_in[8];
    float* out = (float*)d_out;

    __half *Qd, *Kd, *Vd;
    cudaGetSymbolAddress((void**)&Qd, g_Q);
    cudaGetSymbolAddress((void**)&Kd, g_K);
    cudaGetSymbolAddress((void**)&Vd, g_V);

    cudaFuncSetAttribute(qkv_gemm_fused,
                         cudaFuncAttributeMaxDynamicSharedMemorySize,
                         (int)sizeof(GemmSmem));
    cudaFuncSetAttribute(attn_kernel,
                         cudaFuncAttributeMaxDynamicSharedMemorySize,
                         (int)sizeof(AttnSmem));

    // 1) fp32 -> fp16 conversion
    dim3 conv_grid(256, 5);
    convert_fp16<<<conv_grid, 256>>>(former, latter, Wq, Wk, Wv);

    // 2) QKV projection: grid (8, 32, 3), 128x128 tiles
    dim3 gemm_grid(HIDDEN / 128, MTOT / 128, 3);
    qkv_gemm_fused<<<gemm_grid, 256, sizeof(GemmSmem)>>>(bq, bk, bv, Qd, Kd, Vd);

    // 3) attention
    dim3 attn_grid(SEQ / QTILE, HEADS, BATCH);   // (16, 16, 2)
    attn_kernel<<<attn_grid, 256, sizeof(AttnSmem)>>>(Qd, Kd, Vd, mask, out);
}